// round 12
// baseline (speedup 1.0000x reference)
#include <cuda_runtime.h>
#include <math.h>
#include <stdint.h>

// Problem dims
#define BB   64
#define NN   49
#define ENC  2048
#define DEC  512
#define ATT  512
#define EMB  300
#define VV   10000
#define TT   30
#define TP1  31
#define G4   (4 * DEC)           // 2048
#define HWN  (ATT + G4)          // 2560
#define IHW  (EMB + ENC)         // 2348  true ih_w row width

// ---------------- scratch (device globals) ---------------------------------
__device__ float g_uhs[BB * NN * ATT];       // 6.4 MB
__device__ float g_meanf[BB * ENC];
__device__ float g_h[BB * DEC];
__device__ float g_c[BB * DEC];
__device__ float g_hw[BB * HWN];             // [wah(512) | gates_h(2048)]
__device__ float g_H[BB * TT * DEC];         // row = b*TT + t
__device__ float g_wcat[HWN * DEC];          // [W_w ; hh_w]
__device__ float g_hwb[HWN];                 // [W_b ; 0]
__device__ float g_catb[G4];                 // ih_b + hh_b
__device__ float g_FW[BB * NN * G4];         // 25.7 MB: features @ Wc^T
__device__ float g_prex[BB * TT * G4];       // 15.7 MB: emb(x) @ Wx^T + catb
__device__ float g_X[BB * TT * EMB];         // gathered embeddings

__device__ __forceinline__ float fsigmoid(float x) {
    return __fdividef(1.0f, 1.0f + __expf(-x));
}
__device__ __forceinline__ float ftanh(float x) {
    float t = __expf(-2.0f * fabsf(x));
    float r = __fdividef(1.0f - t, 1.0f + t);
    return copysignf(r, x);
}
__device__ __forceinline__ float wred_sum(float v) {
    #pragma unroll
    for (int o = 16; o > 0; o >>= 1) v += __shfl_xor_sync(0xffffffffu, v, o);
    return v;
}
__device__ __forceinline__ uint32_t f2tf32(float x) {
    uint32_t r;
    asm("cvt.rna.tf32.f32 %0, %1;" : "=r"(r) : "f"(x));
    return r;
}
__device__ __forceinline__ void mma_tf32(float* d, const uint32_t* a, const uint32_t* b) {
    asm volatile(
        "mma.sync.aligned.m16n8k8.row.col.f32.tf32.tf32.f32 "
        "{%0,%1,%2,%3}, {%4,%5,%6,%7}, {%8,%9}, {%0,%1,%2,%3};"
        : "+f"(d[0]), "+f"(d[1]), "+f"(d[2]), "+f"(d[3])
        : "r"(a[0]), "r"(a[1]), "r"(a[2]), "r"(a[3]), "r"(b[0]), "r"(b[1]));
}

// guarded float4 load of (row, k0..k0+3) from row-major [rows, >=K] w/ ld
__device__ __forceinline__ float4 ldg4_guard(const float* __restrict__ P,
                                             int row, int ld, int k0,
                                             int rows, int K) {
    float4 v = make_float4(0.f, 0.f, 0.f, 0.f);
    if (row < rows) {
        const float* p = P + (size_t)row * ld + k0;
        if (k0 + 3 < K) {
            v = *reinterpret_cast<const float4*>(p);
        } else {
            if (k0     < K) v.x = p[0];
            if (k0 + 1 < K) v.y = p[1];
            if (k0 + 2 < K) v.z = p[2];
            if (k0 + 3 < K) v.w = p[3];
        }
    }
    return v;
}

// ---------------- tf32 tensor-core GEMM (BK=32, double-buffered, vec IO) ----
// C[M,N] = A[M,K] @ B[N,K]^T + bias. BM=BN=128, BK=32; 8 warps 2(M)x4(N),
// warp tile 64x32. Dynamic smem: sA/sB [2][128][36] words each.
#define TGS   (128 * 36)                 // words per (buf) per matrix
#define SAW(b, r, c) dsm[(b) * TGS + (r) * 36 + (c)]
#define SBW(b, r, c) dsm[2 * TGS + (b) * TGS + (r) * 36 + (c)]
#define TF32_SMEM_BYTES (4 * TGS * 4)    // 73728

__global__ __launch_bounds__(256) void tf32_gemm_nt(
    const float* __restrict__ A, int lda,
    const float* __restrict__ B, int ldb,
    const float* __restrict__ bias, float* __restrict__ C,
    int M, int N, int K)
{
    extern __shared__ uint32_t dsm[];
    const int tid = threadIdx.x;
    const int lane = tid & 31, wid = tid >> 5;
    const int warpM = wid & 1, warpN = wid >> 1;
    const int m0 = blockIdx.y * 128, n0 = blockIdx.x * 128;

    const int r0t = tid >> 3;            // 0..31 (row base, +32*j)
    const int c4  = (tid & 7) << 2;      // 0,4,...,28

    float acc[4][4][4];
    #pragma unroll
    for (int mi = 0; mi < 4; mi++)
        #pragma unroll
        for (int ni = 0; ni < 4; ni++)
            #pragma unroll
            for (int r = 0; r < 4; r++) acc[mi][ni][r] = 0.0f;

    // ---- initial tile -> buffer 0 ----
    #pragma unroll
    for (int j = 0; j < 4; j++) {
        int r = r0t + 32 * j;
        float4 va = ldg4_guard(A, m0 + r, lda, c4, M, K);
        float4 vb = ldg4_guard(B, n0 + r, ldb, c4, N, K);
        uint4 ua = make_uint4(f2tf32(va.x), f2tf32(va.y), f2tf32(va.z), f2tf32(va.w));
        uint4 ub = make_uint4(f2tf32(vb.x), f2tf32(vb.y), f2tf32(vb.z), f2tf32(vb.w));
        *reinterpret_cast<uint4*>(&SAW(0, r, c4)) = ua;
        *reinterpret_cast<uint4*>(&SBW(0, r, c4)) = ub;
    }
    __syncthreads();

    int buf = 0;
    for (int kk = 0; kk < K; kk += 32) {
        const bool has_next = (kk + 32) < K;
        float4 ra[4], rb[4];
        if (has_next) {
            #pragma unroll
            for (int j = 0; j < 4; j++) {
                int r = r0t + 32 * j;
                ra[j] = ldg4_guard(A, m0 + r, lda, kk + 32 + c4, M, K);
                rb[j] = ldg4_guard(B, n0 + r, ldb, kk + 32 + c4, N, K);
            }
        }

        #pragma unroll
        for (int ks = 0; ks < 32; ks += 8) {
            uint32_t af[4][4], bf[4][2];
            #pragma unroll
            for (int mi = 0; mi < 4; mi++) {
                int row = warpM * 64 + mi * 16 + (lane >> 2);
                int col = ks + (lane & 3);
                af[mi][0] = SAW(buf, row, col);
                af[mi][1] = SAW(buf, row + 8, col);
                af[mi][2] = SAW(buf, row, col + 4);
                af[mi][3] = SAW(buf, row + 8, col + 4);
            }
            #pragma unroll
            for (int ni = 0; ni < 4; ni++) {
                int row = warpN * 32 + ni * 8 + (lane >> 2);
                int col = ks + (lane & 3);
                bf[ni][0] = SBW(buf, row, col);
                bf[ni][1] = SBW(buf, row, col + 4);
            }
            #pragma unroll
            for (int mi = 0; mi < 4; mi++)
                #pragma unroll
                for (int ni = 0; ni < 4; ni++)
                    mma_tf32(acc[mi][ni], af[mi], bf[ni]);
        }

        if (has_next) {
            int nb = buf ^ 1;
            #pragma unroll
            for (int j = 0; j < 4; j++) {
                int r = r0t + 32 * j;
                uint4 ua = make_uint4(f2tf32(ra[j].x), f2tf32(ra[j].y),
                                      f2tf32(ra[j].z), f2tf32(ra[j].w));
                uint4 ub = make_uint4(f2tf32(rb[j].x), f2tf32(rb[j].y),
                                      f2tf32(rb[j].z), f2tf32(rb[j].w));
                *reinterpret_cast<uint4*>(&SAW(nb, r, c4)) = ua;
                *reinterpret_cast<uint4*>(&SBW(nb, r, c4)) = ub;
            }
        }
        __syncthreads();
        buf ^= 1;
    }

    #pragma unroll
    for (int mi = 0; mi < 4; mi++) {
        #pragma unroll
        for (int ni = 0; ni < 4; ni++) {
            int row = m0 + warpM * 64 + mi * 16 + (lane >> 2);
            int col = n0 + warpN * 32 + ni * 8 + (lane & 3) * 2;
            float b0 = 0.0f, b1 = 0.0f;
            if (bias) {
                if (col < N)     b0 = bias[col];
                if (col + 1 < N) b1 = bias[col + 1];
            }
            if (row < M) {
                if (col < N)     C[(size_t)row * N + col]     = acc[mi][ni][0] + b0;
                if (col + 1 < N) C[(size_t)row * N + col + 1] = acc[mi][ni][1] + b1;
            }
            if (row + 8 < M) {
                if (col < N)     C[(size_t)(row + 8) * N + col]     = acc[mi][ni][2] + b0;
                if (col + 1 < N) C[(size_t)(row + 8) * N + col + 1] = acc[mi][ni][3] + b1;
            }
        }
    }
}

// ---------------- tf32 GEMM, BM=64 (per-step HW GEMM; no split-K) ----------
// C[64, N] = A[64,K] @ B[N,K]^T + bias. BN=128, BK=32; 8 warps 2(M)x4(N),
// warp tile 32x32.
#define T64A  (64 * 36)
#define T64B  (128 * 36)
#define SA64(b, r, c) dsm[(b) * T64A + (r) * 36 + (c)]
#define SB64(b, r, c) dsm[2 * T64A + (b) * T64B + (r) * 36 + (c)]
#define TF64_SMEM_BYTES ((2 * T64A + 2 * T64B) * 4)   // 55296

__global__ __launch_bounds__(256) void tf32_gemm_nt64(
    const float* __restrict__ A, int lda,
    const float* __restrict__ B, int ldb,
    const float* __restrict__ bias, float* __restrict__ C,
    int N, int K)
{
    extern __shared__ uint32_t dsm[];
    const int tid = threadIdx.x;
    const int lane = tid & 31, wid = tid >> 5;
    const int warpM = wid & 1, warpN = wid >> 1;
    const int n0 = blockIdx.x * 128;

    const int r0t = tid >> 3;            // 0..31
    const int c4  = (tid & 7) << 2;      // 0..28

    float acc[2][4][4];
    #pragma unroll
    for (int mi = 0; mi < 2; mi++)
        #pragma unroll
        for (int ni = 0; ni < 4; ni++)
            #pragma unroll
            for (int r = 0; r < 4; r++) acc[mi][ni][r] = 0.0f;

    // initial tile
    #pragma unroll
    for (int j = 0; j < 2; j++) {
        int r = r0t + 32 * j;
        float4 va = *reinterpret_cast<const float4*>(A + (size_t)r * lda + c4);
        uint4 ua = make_uint4(f2tf32(va.x), f2tf32(va.y), f2tf32(va.z), f2tf32(va.w));
        *reinterpret_cast<uint4*>(&SA64(0, r, c4)) = ua;
    }
    #pragma unroll
    for (int j = 0; j < 4; j++) {
        int r = r0t + 32 * j;
        float4 vb = *reinterpret_cast<const float4*>(B + (size_t)(n0 + r) * ldb + c4);
        uint4 ub = make_uint4(f2tf32(vb.x), f2tf32(vb.y), f2tf32(vb.z), f2tf32(vb.w));
        *reinterpret_cast<uint4*>(&SB64(0, r, c4)) = ub;
    }
    __syncthreads();

    int buf = 0;
    for (int kk = 0; kk < K; kk += 32) {
        const bool has_next = (kk + 32) < K;
        float4 ra[2], rb[4];
        if (has_next) {
            #pragma unroll
            for (int j = 0; j < 2; j++) {
                int r = r0t + 32 * j;
                ra[j] = *reinterpret_cast<const float4*>(A + (size_t)r * lda + kk + 32 + c4);
            }
            #pragma unroll
            for (int j = 0; j < 4; j++) {
                int r = r0t + 32 * j;
                rb[j] = *reinterpret_cast<const float4*>(B + (size_t)(n0 + r) * ldb + kk + 32 + c4);
            }
        }

        #pragma unroll
        for (int ks = 0; ks < 32; ks += 8) {
            uint32_t af[2][4], bf[4][2];
            #pragma unroll
            for (int mi = 0; mi < 2; mi++) {
                int row = warpM * 32 + mi * 16 + (lane >> 2);
                int col = ks + (lane & 3);
                af[mi][0] = SA64(buf, row, col);
                af[mi][1] = SA64(buf, row + 8, col);
                af[mi][2] = SA64(buf, row, col + 4);
                af[mi][3] = SA64(buf, row + 8, col + 4);
            }
            #pragma unroll
            for (int ni = 0; ni < 4; ni++) {
                int row = warpN * 32 + ni * 8 + (lane >> 2);
                int col = ks + (lane & 3);
                bf[ni][0] = SB64(buf, row, col);
                bf[ni][1] = SB64(buf, row, col + 4);
            }
            #pragma unroll
            for (int mi = 0; mi < 2; mi++)
                #pragma unroll
                for (int ni = 0; ni < 4; ni++)
                    mma_tf32(acc[mi][ni], af[mi], bf[ni]);
        }

        if (has_next) {
            int nb = buf ^ 1;
            #pragma unroll
            for (int j = 0; j < 2; j++) {
                int r = r0t + 32 * j;
                uint4 ua = make_uint4(f2tf32(ra[j].x), f2tf32(ra[j].y),
                                      f2tf32(ra[j].z), f2tf32(ra[j].w));
                *reinterpret_cast<uint4*>(&SA64(nb, r, c4)) = ua;
            }
            #pragma unroll
            for (int j = 0; j < 4; j++) {
                int r = r0t + 32 * j;
                uint4 ub = make_uint4(f2tf32(rb[j].x), f2tf32(rb[j].y),
                                      f2tf32(rb[j].z), f2tf32(rb[j].w));
                *reinterpret_cast<uint4*>(&SB64(nb, r, c4)) = ub;
            }
        }
        __syncthreads();
        buf ^= 1;
    }

    #pragma unroll
    for (int mi = 0; mi < 2; mi++) {
        #pragma unroll
        for (int ni = 0; ni < 4; ni++) {
            int row = warpM * 32 + mi * 16 + (lane >> 2);
            int col = n0 + warpN * 32 + ni * 8 + (lane & 3) * 2;
            float b0 = bias[col], b1 = bias[col + 1];
            C[(size_t)row * N + col]           = acc[mi][ni][0] + b0;
            C[(size_t)row * N + col + 1]       = acc[mi][ni][1] + b1;
            C[(size_t)(row + 8) * N + col]     = acc[mi][ni][2] + b0;
            C[(size_t)(row + 8) * N + col + 1] = acc[mi][ni][3] + b1;
        }
    }
}

// ---------------- fp32 SIMT SGEMM (h0/c0) ----------------------------------
template <int BM, int BN, int BK, int TM, int TN, bool ATOMIC>
__global__ __launch_bounds__(256) void sgemm_nt(
    const float* __restrict__ A, const float* __restrict__ B,
    const float* __restrict__ bias, float* __restrict__ C,
    int M, int N, int K, int kChunk)
{
    constexpr int THX = BN / TN;
    constexpr int PAD = 4;
    __shared__ __align__(16) float sA[BK][BM + PAD];
    __shared__ __align__(16) float sB[BK][BN + PAD];

    const int tid = threadIdx.x;
    const int tx  = tid % THX;
    const int ty  = tid / THX;
    const int m0  = blockIdx.y * BM;
    const int n0  = blockIdx.x * BN;
    const int k0  = blockIdx.z * kChunk;
    const int kEnd = min(K, k0 + kChunk);

    float acc[TM][TN];
    #pragma unroll
    for (int i = 0; i < TM; i++)
        #pragma unroll
        for (int j = 0; j < TN; j++) acc[i][j] = 0.0f;

    for (int kk = k0; kk < kEnd; kk += BK) {
        #pragma unroll 4
        for (int i = tid; i < BM * BK; i += 256) {
            int r = i / BK, c = i % BK;
            int gm = m0 + r, gk = kk + c;
            sA[c][r] = (gm < M && gk < kEnd) ? A[(size_t)gm * K + gk] : 0.0f;
        }
        #pragma unroll 4
        for (int i = tid; i < BN * BK; i += 256) {
            int r = i / BK, c = i % BK;
            int gn = n0 + r, gk = kk + c;
            sB[c][r] = (gn < N && gk < kEnd) ? B[(size_t)gn * K + gk] : 0.0f;
        }
        __syncthreads();

        #pragma unroll
        for (int k = 0; k < BK; k++) {
            float af[TM], bf[TN];
            #pragma unroll
            for (int i = 0; i < TM; i += 4) {
                float4 v = *reinterpret_cast<const float4*>(&sA[k][ty * TM + i]);
                af[i] = v.x; af[i+1] = v.y; af[i+2] = v.z; af[i+3] = v.w;
            }
            #pragma unroll
            for (int j = 0; j < TN; j += 4) {
                float4 v = *reinterpret_cast<const float4*>(&sB[k][tx * TN + j]);
                bf[j] = v.x; bf[j+1] = v.y; bf[j+2] = v.z; bf[j+3] = v.w;
            }
            #pragma unroll
            for (int i = 0; i < TM; i++)
                #pragma unroll
                for (int j = 0; j < TN; j++) acc[i][j] = fmaf(af[i], bf[j], acc[i][j]);
        }
        __syncthreads();
    }

    const bool addb = (blockIdx.z == 0) && (bias != nullptr);
    #pragma unroll
    for (int i = 0; i < TM; i++) {
        int gm = m0 + ty * TM + i;
        if (gm >= M) continue;
        #pragma unroll
        for (int j = 0; j < TN; j++) {
            int gn = n0 + tx * TN + j;
            if (gn >= N) continue;
            float v = acc[i][j] + (addb ? bias[gn] : 0.0f);
            if (ATOMIC) atomicAdd(&C[(size_t)gm * N + gn], v);
            else        C[(size_t)gm * N + gn] = v;
        }
    }
}

// ---------------- setup kernels --------------------------------------------
__global__ __launch_bounds__(256) void setup_weights_kernel(
    const float* __restrict__ W_w, const float* __restrict__ W_b,
    const float* __restrict__ hh_w,
    const float* __restrict__ ih_b, const float* __restrict__ hh_b)
{
    int idx = blockIdx.x * 256 + threadIdx.x;
    int total = HWN * DEC;
    if (idx < total) {
        int j = idx / DEC, k = idx - j * DEC;
        g_wcat[idx] = (j < ATT) ? W_w[(size_t)j * DEC + k]
                                : hh_w[(size_t)(j - ATT) * DEC + k];
    }
    if (idx < HWN) g_hwb[idx] = (idx < ATT) ? W_b[idx] : 0.0f;
    if (idx < G4)  g_catb[idx] = ih_b[idx] + hh_b[idx];
}

__global__ __launch_bounds__(256) void gather_x_kernel(
    const float* __restrict__ emb, const int* __restrict__ captions)
{
    int idx = blockIdx.x * 256 + threadIdx.x;   // over BB*TT*EMB
    if (idx >= BB * TT * EMB) return;
    int row = idx / EMB, k = idx - row * EMB;
    int b = row / TT, t = row - b * TT;
    int cap = captions[b * TP1 + t];
    g_X[idx] = emb[(size_t)cap * EMB + k];
}

__global__ __launch_bounds__(256) void mean_kernel(const float* __restrict__ features)
{
    int b = blockIdx.x;
    for (int e = threadIdx.x; e < ENC; e += 256) {
        float s = 0.0f;
        #pragma unroll 7
        for (int n = 0; n < NN; n++) s += features[((size_t)b * NN + n) * ENC + e];
        g_meanf[b * ENC + e] = s * (1.0f / (float)NN);
    }
}

// ---------------- per-step fused attention + gates + LSTM ------------------
__global__ __launch_bounds__(256) void attn_fused_kernel(
    const float* __restrict__ Aw, float* __restrict__ alphas_out, int t)
{
    const int b = blockIdx.x;
    const int tid = threadIdx.x;
    const int warp = tid >> 5, lane = tid & 31;
    __shared__ float sh_wah[ATT];
    __shared__ float sh_aw[ATT];
    __shared__ float sh_alpha[64];
    __shared__ float sh_gates[G4];

    const float* hw = g_hw + b * HWN;
    for (int k = tid; k < ATT; k += 256) {
        sh_wah[k] = hw[k];
        sh_aw[k]  = Aw[k];
    }
    __syncthreads();

    // scores: warp per n (A_b dropped: softmax-invariant)
    for (int n = warp; n < NN; n += 8) {
        const float* u = g_uhs + ((size_t)(b * NN + n)) * ATT;
        float s = 0.0f;
        #pragma unroll
        for (int r = 0; r < 4; r++) {
            int k = r * 128 + lane * 4;
            float4 uv = *reinterpret_cast<const float4*>(u + k);
            s = fmaf(sh_aw[k+0], ftanh(uv.x + sh_wah[k+0]), s);
            s = fmaf(sh_aw[k+1], ftanh(uv.y + sh_wah[k+1]), s);
            s = fmaf(sh_aw[k+2], ftanh(uv.z + sh_wah[k+2]), s);
            s = fmaf(sh_aw[k+3], ftanh(uv.w + sh_wah[k+3]), s);
        }
        s = wred_sum(s);
        if (lane == 0) sh_alpha[n] = s;
    }
    __syncthreads();

    if (tid < 32) {
        float m = -1e30f;
        for (int n = tid; n < NN; n += 32) m = fmaxf(m, sh_alpha[n]);
        #pragma unroll
        for (int o = 16; o > 0; o >>= 1) m = fmaxf(m, __shfl_xor_sync(0xffffffffu, m, o));
        float s = 0.0f;
        for (int n = tid; n < NN; n += 32) { float e = __expf(sh_alpha[n] - m); sh_alpha[n] = e; s += e; }
        s = wred_sum(s);
        float inv = __fdividef(1.0f, s);
        for (int n = tid; n < NN; n += 32) sh_alpha[n] *= inv;
    }
    __syncthreads();

    for (int n = tid; n < NN; n += 256)
        alphas_out[((size_t)b * TT + t) * NN + n] = sh_alpha[n];

    // gates: thread handles 8 consecutive gate dims (catb already in prex)
    {
        const float* fw = g_FW + (size_t)b * NN * G4;
        const float* px = g_prex + ((size_t)(b * TT + t)) * G4;
        int d0 = tid * 8;
        float4 a0 = *reinterpret_cast<const float4*>(px + d0);
        float4 a1 = *reinterpret_cast<const float4*>(px + d0 + 4);
        float4 hh0 = *reinterpret_cast<const float4*>(hw + ATT + d0);
        float4 hh1 = *reinterpret_cast<const float4*>(hw + ATT + d0 + 4);
        a0.x += hh0.x; a0.y += hh0.y; a0.z += hh0.z; a0.w += hh0.w;
        a1.x += hh1.x; a1.y += hh1.y; a1.z += hh1.z; a1.w += hh1.w;
        #pragma unroll 7
        for (int n = 0; n < NN; n++) {
            float an = sh_alpha[n];
            float4 f0 = *reinterpret_cast<const float4*>(fw + (size_t)n * G4 + d0);
            float4 f1 = *reinterpret_cast<const float4*>(fw + (size_t)n * G4 + d0 + 4);
            a0.x = fmaf(an, f0.x, a0.x); a0.y = fmaf(an, f0.y, a0.y);
            a0.z = fmaf(an, f0.z, a0.z); a0.w = fmaf(an, f0.w, a0.w);
            a1.x = fmaf(an, f1.x, a1.x); a1.y = fmaf(an, f1.y, a1.y);
            a1.z = fmaf(an, f1.z, a1.z); a1.w = fmaf(an, f1.w, a1.w);
        }
        *reinterpret_cast<float4*>(sh_gates + d0)     = a0;
        *reinterpret_cast<float4*>(sh_gates + d0 + 4) = a1;
    }
    __syncthreads();

    // LSTM pointwise
    for (int d = tid; d < DEC; d += 256) {
        float gi = fsigmoid(sh_gates[d]);
        float gf = fsigmoid(sh_gates[DEC + d]);
        float gg = ftanh(sh_gates[2 * DEC + d]);
        float go = fsigmoid(sh_gates[3 * DEC + d]);
        float c = fmaf(gf, g_c[b * DEC + d], gi * gg);
        float h = go * ftanh(c);
        g_c[b * DEC + d] = c;
        g_h[b * DEC + d] = h;
        g_H[((size_t)b * TT + t) * DEC + d] = h;
    }
}

// ---------------- host orchestration ---------------------------------------
extern "C" void kernel_launch(void* const* d_in, const int* in_sizes, int n_in,
                              void* d_out, int out_size)
{
    const float* features = (const float*)d_in[0];
    const int*   captions = (const int*)  d_in[1];
    const float* emb      = (const float*)d_in[2];
    const float* U_w      = (const float*)d_in[3];
    const float* U_b      = (const float*)d_in[4];
    const float* W_w      = (const float*)d_in[5];
    const float* W_b      = (const float*)d_in[6];
    const float* A_w      = (const float*)d_in[7];
    const float* A_b      = (const float*)d_in[8];  (void)A_b;
    const float* initH_w  = (const float*)d_in[9];
    const float* initH_b  = (const float*)d_in[10];
    const float* initC_w  = (const float*)d_in[11];
    const float* initC_b  = (const float*)d_in[12];
    const float* ih_w     = (const float*)d_in[13];
    const float* ih_b     = (const float*)d_in[14];
    const float* hh_w     = (const float*)d_in[15];
    const float* hh_b     = (const float*)d_in[16];
    const float* fcn_w    = (const float*)d_in[17];
    const float* fcn_b    = (const float*)d_in[18];

    float* preds  = (float*)d_out;                        // [64,30,10000]
    float* alphas = (float*)d_out + (size_t)BB * TT * VV; // [64,30,49]

    float *p_uhs, *p_meanf, *p_h, *p_c, *p_hw, *p_H, *p_wcat, *p_hwb, *p_catb,
          *p_FW, *p_prex, *p_X;
    cudaGetSymbolAddress((void**)&p_uhs,   g_uhs);
    cudaGetSymbolAddress((void**)&p_meanf, g_meanf);
    cudaGetSymbolAddress((void**)&p_h,     g_h);
    cudaGetSymbolAddress((void**)&p_c,     g_c);
    cudaGetSymbolAddress((void**)&p_hw,    g_hw);
    cudaGetSymbolAddress((void**)&p_H,     g_H);
    cudaGetSymbolAddress((void**)&p_wcat,  g_wcat);
    cudaGetSymbolAddress((void**)&p_hwb,   g_hwb);
    cudaGetSymbolAddress((void**)&p_catb,  g_catb);
    cudaGetSymbolAddress((void**)&p_FW,    g_FW);
    cudaGetSymbolAddress((void**)&p_prex,  g_prex);
    cudaGetSymbolAddress((void**)&p_X,     g_X);

    cudaFuncSetAttribute(tf32_gemm_nt,
                         cudaFuncAttributeMaxDynamicSharedMemorySize,
                         TF32_SMEM_BYTES);
    cudaFuncSetAttribute(tf32_gemm_nt64,
                         cudaFuncAttributeMaxDynamicSharedMemorySize,
                         TF64_SMEM_BYTES);

    // --- launches 0..5 (ncu -s 5 captures #5 = FW tf32 GEMM) ---
    setup_weights_kernel<<<(HWN * DEC + 255) / 256, 256>>>(W_w, W_b, hh_w, ih_b, hh_b);   // 0
    gather_x_kernel<<<(BB * TT * EMB + 255) / 256, 256>>>(emb, captions);                 // 1
    mean_kernel<<<BB, 256>>>(features);                                                   // 2
    // u_hs = features @ U_w^T + U_b                [3136, 512]
    tf32_gemm_nt<<<dim3(4, 25), 256, TF32_SMEM_BYTES>>>(                                  // 3
        features, ENC, U_w, ENC, U_b, p_uhs, BB * NN, ATT, ENC);
    // pre_x = X @ Wx^T + catb (Wx = ih_w[:,0:300]) [1920, 2048]
    tf32_gemm_nt<<<dim3(16, 15), 256, TF32_SMEM_BYTES>>>(                                 // 4
        p_X, EMB, ih_w, IHW, p_catb, p_prex, BB * TT, G4, EMB);
    // FW = features @ Wc^T  (Wc = ih_w[:,300:2348]) [3136, 2048]
    tf32_gemm_nt<<<dim3(16, 25), 256, TF32_SMEM_BYTES>>>(                                 // 5
        features, ENC, ih_w + EMB, IHW, nullptr, p_FW, BB * NN, G4, ENC);

    // h0/c0 (fp32 split-K)
    cudaMemsetAsync(p_h, 0, (size_t)BB * DEC * sizeof(float));
    cudaMemsetAsync(p_c, 0, (size_t)BB * DEC * sizeof(float));
    sgemm_nt<64, 64, 16, 4, 4, true><<<dim3(8, 1, 32), 256>>>(
        p_meanf, initH_w, initH_b, p_h, BB, DEC, ENC, ENC / 32);
    sgemm_nt<64, 64, 16, 4, 4, true><<<dim3(8, 1, 32), 256>>>(
        p_meanf, initC_w, initC_b, p_c, BB, DEC, ENC, ENC / 32);

    // --- serial loop: 2 nodes per step ---
    for (int t = 0; t < TT; t++) {
        // HW = h @ [W_w; hh_w]^T + [W_b; 0]  (tf32, no split-K, no atomics)
        tf32_gemm_nt64<<<dim3(HWN / 128, 1), 256, TF64_SMEM_BYTES>>>(
            p_h, DEC, p_wcat, DEC, p_hwb, p_hw, HWN, DEC);

        attn_fused_kernel<<<BB, 256>>>(A_w, alphas, t);
    }

    // preds = H @ fcn_w^T + fcn_b   [1920, 10000]  (tf32 tensor)
    tf32_gemm_nt<<<dim3((VV + 127) / 128, (BB * TT + 127) / 128), 256, TF32_SMEM_BYTES>>>(
        p_H, DEC, fcn_w, DEC, fcn_b, preds, BB * TT, VV, DEC);
}

// round 16
// speedup vs baseline: 1.1749x; 1.1749x over previous
#include <cuda_runtime.h>
#include <math.h>
#include <stdint.h>

// Problem dims
#define BB   64
#define NN   49
#define ENC  2048
#define DEC  512
#define ATT  512
#define EMB  300
#define VV   10000
#define TT   30
#define TP1  31
#define G4   (4 * DEC)           // 2048
#define HWN  (ATT + G4)          // 2560
#define IHW  (EMB + ENC)         // 2348  true ih_w row width

// ---------------- scratch (device globals) ---------------------------------
__device__ float g_uhs[BB * NN * ATT];       // 6.4 MB
__device__ float g_meanf[BB * ENC];
__device__ float g_h[BB * DEC];
__device__ float g_c[BB * DEC];
__device__ float g_hw[BB * HWN];             // [wah(512) | gates_h(2048)]
__device__ float g_H[BB * TT * DEC];         // row = b*TT + t
__device__ float g_wcat[HWN * DEC];          // [W_w ; hh_w]
__device__ float g_hwb[HWN];                 // [W_b ; 0]
__device__ float g_catb[G4];                 // ih_b + hh_b
__device__ float g_FW[BB * NN * G4];         // 25.7 MB: features @ Wc^T
__device__ float g_prex[BB * TT * G4];       // 15.7 MB: emb(x) @ Wx^T + catb
__device__ float g_X[BB * TT * EMB];         // gathered embeddings

__device__ __forceinline__ float fsigmoid(float x) {
    return __fdividef(1.0f, 1.0f + __expf(-x));
}
__device__ __forceinline__ float ftanh(float x) {
    float t = __expf(-2.0f * fabsf(x));
    float r = __fdividef(1.0f - t, 1.0f + t);
    return copysignf(r, x);
}
__device__ __forceinline__ float wred_sum(float v) {
    #pragma unroll
    for (int o = 16; o > 0; o >>= 1) v += __shfl_xor_sync(0xffffffffu, v, o);
    return v;
}
__device__ __forceinline__ uint32_t f2tf32(float x) {
    uint32_t r;
    asm("cvt.rna.tf32.f32 %0, %1;" : "=r"(r) : "f"(x));
    return r;
}
__device__ __forceinline__ void mma_tf32(float* d, const uint32_t* a, const uint32_t* b) {
    asm volatile(
        "mma.sync.aligned.m16n8k8.row.col.f32.tf32.tf32.f32 "
        "{%0,%1,%2,%3}, {%4,%5,%6,%7}, {%8,%9}, {%0,%1,%2,%3};"
        : "+f"(d[0]), "+f"(d[1]), "+f"(d[2]), "+f"(d[3])
        : "r"(a[0]), "r"(a[1]), "r"(a[2]), "r"(a[3]), "r"(b[0]), "r"(b[1]));
}

// guarded float4 load of (row, k0..k0+3) from row-major [rows, >=K] w/ ld
__device__ __forceinline__ float4 ldg4_guard(const float* __restrict__ P,
                                             int row, int ld, int k0,
                                             int rows, int K) {
    float4 v = make_float4(0.f, 0.f, 0.f, 0.f);
    if (row < rows) {
        const float* p = P + (size_t)row * ld + k0;
        if (k0 + 3 < K) {
            v = *reinterpret_cast<const float4*>(p);
        } else {
            if (k0     < K) v.x = p[0];
            if (k0 + 1 < K) v.y = p[1];
            if (k0 + 2 < K) v.z = p[2];
            if (k0 + 3 < K) v.w = p[3];
        }
    }
    return v;
}

// ---------------- tf32 tensor-core GEMM (BK=32, double-buffered, vec IO) ----
// C[M,N] = A[M,K] @ B[N,K]^T + bias. BM=BN=128, BK=32; 8 warps 2(M)x4(N),
// warp tile 64x32. Dynamic smem: sA/sB [2][128][36] words each.
// __launch_bounds__(256, 2): cap regs at 128 so 2 CTAs/SM fit (occupancy fix).
#define TGS   (128 * 36)                 // words per (buf) per matrix
#define SAW(b, r, c) dsm[(b) * TGS + (r) * 36 + (c)]
#define SBW(b, r, c) dsm[2 * TGS + (b) * TGS + (r) * 36 + (c)]
#define TF32_SMEM_BYTES (4 * TGS * 4)    // 73728

__global__ __launch_bounds__(256, 2) void tf32_gemm_nt(
    const float* __restrict__ A, int lda,
    const float* __restrict__ B, int ldb,
    const float* __restrict__ bias, float* __restrict__ C,
    int M, int N, int K)
{
    extern __shared__ uint32_t dsm[];
    const int tid = threadIdx.x;
    const int lane = tid & 31, wid = tid >> 5;
    const int warpM = wid & 1, warpN = wid >> 1;
    const int m0 = blockIdx.y * 128, n0 = blockIdx.x * 128;

    const int r0t = tid >> 3;            // 0..31 (row base, +32*j)
    const int c4  = (tid & 7) << 2;      // 0,4,...,28

    float acc[4][4][4];
    #pragma unroll
    for (int mi = 0; mi < 4; mi++)
        #pragma unroll
        for (int ni = 0; ni < 4; ni++)
            #pragma unroll
            for (int r = 0; r < 4; r++) acc[mi][ni][r] = 0.0f;

    // ---- initial tile -> buffer 0 ----
    #pragma unroll
    for (int j = 0; j < 4; j++) {
        int r = r0t + 32 * j;
        float4 va = ldg4_guard(A, m0 + r, lda, c4, M, K);
        float4 vb = ldg4_guard(B, n0 + r, ldb, c4, N, K);
        uint4 ua = make_uint4(f2tf32(va.x), f2tf32(va.y), f2tf32(va.z), f2tf32(va.w));
        uint4 ub = make_uint4(f2tf32(vb.x), f2tf32(vb.y), f2tf32(vb.z), f2tf32(vb.w));
        *reinterpret_cast<uint4*>(&SAW(0, r, c4)) = ua;
        *reinterpret_cast<uint4*>(&SBW(0, r, c4)) = ub;
    }
    __syncthreads();

    int buf = 0;
    for (int kk = 0; kk < K; kk += 32) {
        const bool has_next = (kk + 32) < K;
        float4 ra[4], rb[4];
        if (has_next) {
            #pragma unroll
            for (int j = 0; j < 4; j++) {
                int r = r0t + 32 * j;
                ra[j] = ldg4_guard(A, m0 + r, lda, kk + 32 + c4, M, K);
                rb[j] = ldg4_guard(B, n0 + r, ldb, kk + 32 + c4, N, K);
            }
        }

        #pragma unroll
        for (int ks = 0; ks < 32; ks += 8) {
            uint32_t af[4][4], bf[4][2];
            #pragma unroll
            for (int mi = 0; mi < 4; mi++) {
                int row = warpM * 64 + mi * 16 + (lane >> 2);
                int col = ks + (lane & 3);
                af[mi][0] = SAW(buf, row, col);
                af[mi][1] = SAW(buf, row + 8, col);
                af[mi][2] = SAW(buf, row, col + 4);
                af[mi][3] = SAW(buf, row + 8, col + 4);
            }
            #pragma unroll
            for (int ni = 0; ni < 4; ni++) {
                int row = warpN * 32 + ni * 8 + (lane >> 2);
                int col = ks + (lane & 3);
                bf[ni][0] = SBW(buf, row, col);
                bf[ni][1] = SBW(buf, row, col + 4);
            }
            #pragma unroll
            for (int mi = 0; mi < 4; mi++)
                #pragma unroll
                for (int ni = 0; ni < 4; ni++)
                    mma_tf32(acc[mi][ni], af[mi], bf[ni]);
        }

        if (has_next) {
            int nb = buf ^ 1;
            #pragma unroll
            for (int j = 0; j < 4; j++) {
                int r = r0t + 32 * j;
                uint4 ua = make_uint4(f2tf32(ra[j].x), f2tf32(ra[j].y),
                                      f2tf32(ra[j].z), f2tf32(ra[j].w));
                uint4 ub = make_uint4(f2tf32(rb[j].x), f2tf32(rb[j].y),
                                      f2tf32(rb[j].z), f2tf32(rb[j].w));
                *reinterpret_cast<uint4*>(&SAW(nb, r, c4)) = ua;
                *reinterpret_cast<uint4*>(&SBW(nb, r, c4)) = ub;
            }
        }
        __syncthreads();
        buf ^= 1;
    }

    #pragma unroll
    for (int mi = 0; mi < 4; mi++) {
        #pragma unroll
        for (int ni = 0; ni < 4; ni++) {
            int row = m0 + warpM * 64 + mi * 16 + (lane >> 2);
            int col = n0 + warpN * 32 + ni * 8 + (lane & 3) * 2;
            float b0 = 0.0f, b1 = 0.0f;
            if (bias) {
                if (col < N)     b0 = bias[col];
                if (col + 1 < N) b1 = bias[col + 1];
            }
            if (row < M) {
                if (col < N)     C[(size_t)row * N + col]     = acc[mi][ni][0] + b0;
                if (col + 1 < N) C[(size_t)row * N + col + 1] = acc[mi][ni][1] + b1;
            }
            if (row + 8 < M) {
                if (col < N)     C[(size_t)(row + 8) * N + col]     = acc[mi][ni][2] + b0;
                if (col + 1 < N) C[(size_t)(row + 8) * N + col + 1] = acc[mi][ni][3] + b1;
            }
        }
    }
}

// ---------------- fp32 SIMT SGEMM (h0/c0 + per-step HW GEMM) ---------------
template <int BM, int BN, int BK, int TM, int TN, bool ATOMIC>
__global__ __launch_bounds__(256) void sgemm_nt(
    const float* __restrict__ A, const float* __restrict__ B,
    const float* __restrict__ bias, float* __restrict__ C,
    int M, int N, int K, int kChunk)
{
    constexpr int THX = BN / TN;
    constexpr int PAD = 4;
    __shared__ __align__(16) float sA[BK][BM + PAD];
    __shared__ __align__(16) float sB[BK][BN + PAD];

    const int tid = threadIdx.x;
    const int tx  = tid % THX;
    const int ty  = tid / THX;
    const int m0  = blockIdx.y * BM;
    const int n0  = blockIdx.x * BN;
    const int k0  = blockIdx.z * kChunk;
    const int kEnd = min(K, k0 + kChunk);

    float acc[TM][TN];
    #pragma unroll
    for (int i = 0; i < TM; i++)
        #pragma unroll
        for (int j = 0; j < TN; j++) acc[i][j] = 0.0f;

    for (int kk = k0; kk < kEnd; kk += BK) {
        #pragma unroll 4
        for (int i = tid; i < BM * BK; i += 256) {
            int r = i / BK, c = i % BK;
            int gm = m0 + r, gk = kk + c;
            sA[c][r] = (gm < M && gk < kEnd) ? A[(size_t)gm * K + gk] : 0.0f;
        }
        #pragma unroll 4
        for (int i = tid; i < BN * BK; i += 256) {
            int r = i / BK, c = i % BK;
            int gn = n0 + r, gk = kk + c;
            sB[c][r] = (gn < N && gk < kEnd) ? B[(size_t)gn * K + gk] : 0.0f;
        }
        __syncthreads();

        #pragma unroll
        for (int k = 0; k < BK; k++) {
            float af[TM], bf[TN];
            #pragma unroll
            for (int i = 0; i < TM; i += 4) {
                float4 v = *reinterpret_cast<const float4*>(&sA[k][ty * TM + i]);
                af[i] = v.x; af[i+1] = v.y; af[i+2] = v.z; af[i+3] = v.w;
            }
            #pragma unroll
            for (int j = 0; j < TN; j += 4) {
                float4 v = *reinterpret_cast<const float4*>(&sB[k][tx * TN + j]);
                bf[j] = v.x; bf[j+1] = v.y; bf[j+2] = v.z; bf[j+3] = v.w;
            }
            #pragma unroll
            for (int i = 0; i < TM; i++)
                #pragma unroll
                for (int j = 0; j < TN; j++) acc[i][j] = fmaf(af[i], bf[j], acc[i][j]);
        }
        __syncthreads();
    }

    const bool addb = (blockIdx.z == 0) && (bias != nullptr);
    #pragma unroll
    for (int i = 0; i < TM; i++) {
        int gm = m0 + ty * TM + i;
        if (gm >= M) continue;
        #pragma unroll
        for (int j = 0; j < TN; j++) {
            int gn = n0 + tx * TN + j;
            if (gn >= N) continue;
            float v = acc[i][j] + (addb ? bias[gn] : 0.0f);
            if (ATOMIC) atomicAdd(&C[(size_t)gm * N + gn], v);
            else        C[(size_t)gm * N + gn] = v;
        }
    }
}

// ---------------- setup kernels --------------------------------------------
__global__ __launch_bounds__(256) void setup_weights_kernel(
    const float* __restrict__ W_w, const float* __restrict__ W_b,
    const float* __restrict__ hh_w,
    const float* __restrict__ ih_b, const float* __restrict__ hh_b)
{
    int idx = blockIdx.x * 256 + threadIdx.x;
    int total = HWN * DEC;
    if (idx < total) {
        int j = idx / DEC, k = idx - j * DEC;
        g_wcat[idx] = (j < ATT) ? W_w[(size_t)j * DEC + k]
                                : hh_w[(size_t)(j - ATT) * DEC + k];
    }
    if (idx < HWN) g_hwb[idx] = (idx < ATT) ? W_b[idx] : 0.0f;
    if (idx < G4)  g_catb[idx] = ih_b[idx] + hh_b[idx];
}

__global__ __launch_bounds__(256) void gather_x_kernel(
    const float* __restrict__ emb, const int* __restrict__ captions)
{
    int idx = blockIdx.x * 256 + threadIdx.x;   // over BB*TT*EMB
    if (idx >= BB * TT * EMB) return;
    int row = idx / EMB, k = idx - row * EMB;
    int b = row / TT, t = row - b * TT;
    int cap = captions[b * TP1 + t];
    g_X[idx] = emb[(size_t)cap * EMB + k];
}

__global__ __launch_bounds__(256) void mean_kernel(const float* __restrict__ features)
{
    int b = blockIdx.x;
    for (int e = threadIdx.x; e < ENC; e += 256) {
        float s = 0.0f;
        #pragma unroll 7
        for (int n = 0; n < NN; n++) s += features[((size_t)b * NN + n) * ENC + e];
        g_meanf[b * ENC + e] = s * (1.0f / (float)NN);
    }
}

// ---------------- per-step fused attention + gates + LSTM ------------------
__global__ __launch_bounds__(256) void attn_fused_kernel(
    const float* __restrict__ Aw, float* __restrict__ alphas_out, int t)
{
    const int b = blockIdx.x;
    const int tid = threadIdx.x;
    const int warp = tid >> 5, lane = tid & 31;
    __shared__ float sh_wah[ATT];
    __shared__ float sh_aw[ATT];
    __shared__ float sh_alpha[64];
    __shared__ float sh_gates[G4];

    float* hw = g_hw + b * HWN;
    for (int k = tid; k < ATT; k += 256) {
        sh_wah[k] = hw[k];
        sh_aw[k]  = Aw[k];
    }
    __syncthreads();

    // scores: warp per n (A_b dropped: softmax-invariant)
    for (int n = warp; n < NN; n += 8) {
        const float* u = g_uhs + ((size_t)(b * NN + n)) * ATT;
        float s = 0.0f;
        #pragma unroll
        for (int r = 0; r < 4; r++) {
            int k = r * 128 + lane * 4;
            float4 uv = *reinterpret_cast<const float4*>(u + k);
            s = fmaf(sh_aw[k+0], ftanh(uv.x + sh_wah[k+0]), s);
            s = fmaf(sh_aw[k+1], ftanh(uv.y + sh_wah[k+1]), s);
            s = fmaf(sh_aw[k+2], ftanh(uv.z + sh_wah[k+2]), s);
            s = fmaf(sh_aw[k+3], ftanh(uv.w + sh_wah[k+3]), s);
        }
        s = wred_sum(s);
        if (lane == 0) sh_alpha[n] = s;
    }
    __syncthreads();

    if (tid < 32) {
        float m = -1e30f;
        for (int n = tid; n < NN; n += 32) m = fmaxf(m, sh_alpha[n]);
        #pragma unroll
        for (int o = 16; o > 0; o >>= 1) m = fmaxf(m, __shfl_xor_sync(0xffffffffu, m, o));
        float s = 0.0f;
        for (int n = tid; n < NN; n += 32) { float e = __expf(sh_alpha[n] - m); sh_alpha[n] = e; s += e; }
        s = wred_sum(s);
        float inv = __fdividef(1.0f, s);
        for (int n = tid; n < NN; n += 32) sh_alpha[n] *= inv;
    }
    __syncthreads();

    for (int n = tid; n < NN; n += 256)
        alphas_out[((size_t)b * TT + t) * NN + n] = sh_alpha[n];

    // gates: thread handles 8 consecutive gate dims (catb already in prex)
    {
        const float* fw = g_FW + (size_t)b * NN * G4;
        const float* px = g_prex + ((size_t)(b * TT + t)) * G4;
        int d0 = tid * 8;
        float4 a0 = *reinterpret_cast<const float4*>(px + d0);
        float4 a1 = *reinterpret_cast<const float4*>(px + d0 + 4);
        float4 hh0 = *reinterpret_cast<const float4*>(hw + ATT + d0);
        float4 hh1 = *reinterpret_cast<const float4*>(hw + ATT + d0 + 4);
        a0.x += hh0.x; a0.y += hh0.y; a0.z += hh0.z; a0.w += hh0.w;
        a1.x += hh1.x; a1.y += hh1.y; a1.z += hh1.z; a1.w += hh1.w;
        #pragma unroll 7
        for (int n = 0; n < NN; n++) {
            float an = sh_alpha[n];
            float4 f0 = *reinterpret_cast<const float4*>(fw + (size_t)n * G4 + d0);
            float4 f1 = *reinterpret_cast<const float4*>(fw + (size_t)n * G4 + d0 + 4);
            a0.x = fmaf(an, f0.x, a0.x); a0.y = fmaf(an, f0.y, a0.y);
            a0.z = fmaf(an, f0.z, a0.z); a0.w = fmaf(an, f0.w, a0.w);
            a1.x = fmaf(an, f1.x, a1.x); a1.y = fmaf(an, f1.y, a1.y);
            a1.z = fmaf(an, f1.z, a1.z); a1.w = fmaf(an, f1.w, a1.w);
        }
        *reinterpret_cast<float4*>(sh_gates + d0)     = a0;
        *reinterpret_cast<float4*>(sh_gates + d0 + 4) = a1;
    }
    __syncthreads();

    // LSTM pointwise + zero g_hw for next step's atomics
    for (int d = tid; d < DEC; d += 256) {
        float gi = fsigmoid(sh_gates[d]);
        float gf = fsigmoid(sh_gates[DEC + d]);
        float gg = ftanh(sh_gates[2 * DEC + d]);
        float go = fsigmoid(sh_gates[3 * DEC + d]);
        float c = fmaf(gf, g_c[b * DEC + d], gi * gg);
        float h = go * ftanh(c);
        g_c[b * DEC + d] = c;
        g_h[b * DEC + d] = h;
        g_H[((size_t)b * TT + t) * DEC + d] = h;
    }
    for (int k = tid; k < HWN; k += 256) hw[k] = 0.0f;
}

// ---------------- host orchestration ---------------------------------------
extern "C" void kernel_launch(void* const* d_in, const int* in_sizes, int n_in,
                              void* d_out, int out_size)
{
    const float* features = (const float*)d_in[0];
    const int*   captions = (const int*)  d_in[1];
    const float* emb      = (const float*)d_in[2];
    const float* U_w      = (const float*)d_in[3];
    const float* U_b      = (const float*)d_in[4];
    const float* W_w      = (const float*)d_in[5];
    const float* W_b      = (const float*)d_in[6];
    const float* A_w      = (const float*)d_in[7];
    const float* A_b      = (const float*)d_in[8];  (void)A_b;
    const float* initH_w  = (const float*)d_in[9];
    const float* initH_b  = (const float*)d_in[10];
    const float* initC_w  = (const float*)d_in[11];
    const float* initC_b  = (const float*)d_in[12];
    const float* ih_w     = (const float*)d_in[13];
    const float* ih_b     = (const float*)d_in[14];
    const float* hh_w     = (const float*)d_in[15];
    const float* hh_b     = (const float*)d_in[16];
    const float* fcn_w    = (const float*)d_in[17];
    const float* fcn_b    = (const float*)d_in[18];

    float* preds  = (float*)d_out;                        // [64,30,10000]
    float* alphas = (float*)d_out + (size_t)BB * TT * VV; // [64,30,49]

    float *p_uhs, *p_meanf, *p_h, *p_c, *p_hw, *p_H, *p_wcat, *p_hwb, *p_catb,
          *p_FW, *p_prex, *p_X;
    cudaGetSymbolAddress((void**)&p_uhs,   g_uhs);
    cudaGetSymbolAddress((void**)&p_meanf, g_meanf);
    cudaGetSymbolAddress((void**)&p_h,     g_h);
    cudaGetSymbolAddress((void**)&p_c,     g_c);
    cudaGetSymbolAddress((void**)&p_hw,    g_hw);
    cudaGetSymbolAddress((void**)&p_H,     g_H);
    cudaGetSymbolAddress((void**)&p_wcat,  g_wcat);
    cudaGetSymbolAddress((void**)&p_hwb,   g_hwb);
    cudaGetSymbolAddress((void**)&p_catb,  g_catb);
    cudaGetSymbolAddress((void**)&p_FW,    g_FW);
    cudaGetSymbolAddress((void**)&p_prex,  g_prex);
    cudaGetSymbolAddress((void**)&p_X,     g_X);

    cudaFuncSetAttribute(tf32_gemm_nt,
                         cudaFuncAttributeMaxDynamicSharedMemorySize,
                         TF32_SMEM_BYTES);

    // --- launches 0..5 (ncu -s 5 lands inside the tf32 GEMM group) ---
    setup_weights_kernel<<<(HWN * DEC + 255) / 256, 256>>>(W_w, W_b, hh_w, ih_b, hh_b);   // 0
    gather_x_kernel<<<(BB * TT * EMB + 255) / 256, 256>>>(emb, captions);                 // 1
    mean_kernel<<<BB, 256>>>(features);                                                   // 2
    // u_hs = features @ U_w^T + U_b                [3136, 512]
    tf32_gemm_nt<<<dim3(4, 25), 256, TF32_SMEM_BYTES>>>(                                  // 3
        features, ENC, U_w, ENC, U_b, p_uhs, BB * NN, ATT, ENC);
    // pre_x = X @ Wx^T + catb (Wx = ih_w[:,0:300]) [1920, 2048]
    tf32_gemm_nt<<<dim3(16, 15), 256, TF32_SMEM_BYTES>>>(                                 // 4
        p_X, EMB, ih_w, IHW, p_catb, p_prex, BB * TT, G4, EMB);
    // FW = features @ Wc^T  (Wc = ih_w[:,300:2348]) [3136, 2048]
    tf32_gemm_nt<<<dim3(16, 25), 256, TF32_SMEM_BYTES>>>(                                 // 5
        features, ENC, ih_w + EMB, IHW, nullptr, p_FW, BB * NN, G4, ENC);

    // h0/c0 (fp32 split-K) + zero the HW accumulation buffer once
    cudaMemsetAsync(p_h, 0, (size_t)BB * DEC * sizeof(float));
    cudaMemsetAsync(p_c, 0, (size_t)BB * DEC * sizeof(float));
    cudaMemsetAsync(p_hw, 0, (size_t)BB * HWN * sizeof(float));
    sgemm_nt<64, 64, 16, 4, 4, true><<<dim3(8, 1, 32), 256>>>(
        p_meanf, initH_w, initH_b, p_h, BB, DEC, ENC, ENC / 32);
    sgemm_nt<64, 64, 16, 4, 4, true><<<dim3(8, 1, 32), 256>>>(
        p_meanf, initC_w, initC_b, p_c, BB, DEC, ENC, ENC / 32);

    // --- serial loop: 2 nodes per step ---
    for (int t = 0; t < TT; t++) {
        // HW = h @ [W_w; hh_w]^T + [W_b; 0]  (fp32 split-K z=16, 640 blocks;
        // g_hw zeroed by previous attn_fused / initial memset)
        sgemm_nt<64, 64, 16, 4, 4, true><<<dim3(HWN / 64, 1, 16), 256>>>(
            p_h, p_wcat, p_hwb, p_hw, BB, HWN, DEC, DEC / 16);

        attn_fused_kernel<<<BB, 256>>>(A_w, alphas, t);
    }

    // preds = H @ fcn_w^T + fcn_b   [1920, 10000]  (tf32 tensor)
    tf32_gemm_nt<<<dim3((VV + 127) / 128, (BB * TT + 127) / 128), 256, TF32_SMEM_BYTES>>>(
        p_H, DEC, fcn_w, DEC, fcn_b, preds, BB * TT, VV, DEC);
}